// round 4
// baseline (speedup 1.0000x reference)
#include <cuda_runtime.h>

#define NN 100000
#define DF 16

// ---- device scratch (no allocations allowed) ----
__device__ float g_D[NN * DF];
__device__ float g_PrS[NN * DF];
__device__ float g_PcS[NN * DF];
__device__ int   g_rcnt[NN];
__device__ int   g_ccnt[NN];
__device__ float g_rowb[NN * DF];
__device__ float g_colb[NN * DF];
__device__ float g_diagb[NN * DF];
__device__ float g_pdsum[DF];
__device__ float g_pasum[DF];

__device__ __forceinline__ void red4(float* p, float4 v) {
    asm volatile("red.global.add.v4.f32 [%0], {%1,%2,%3,%4};"
                 :: "l"(p), "f"(v.x), "f"(v.y), "f"(v.z), "f"(v.w) : "memory");
}

// ---- K0: zero scratch (float4-vectorized) ----
__global__ void k_zero() {
    int tid = blockIdx.x * blockDim.x + threadIdx.x;
    int stride = gridDim.x * blockDim.x;
    float4 z = make_float4(0.f, 0.f, 0.f, 0.f);
    for (int t = tid; t < NN * DF / 4; t += stride) {
        ((float4*)g_PrS)[t] = z;
        ((float4*)g_PcS)[t] = z;
        ((float4*)g_D)[t]   = z;
    }
    for (int t = tid; t < NN; t += stride) { g_rcnt[t] = 0; g_ccnt[t] = 0; }
    if (blockIdx.x == 0 && threadIdx.x < DF) {
        g_pdsum[threadIdx.x] = 0.f; g_pasum[threadIdx.x] = 0.f;
    }
}

// ---- K1: pooling pass (segment sums + counts + global sums) ----
__global__ void __launch_bounds__(256) k_pool(
    const float* __restrict__ vals, const int* __restrict__ row,
    const int* __restrict__ col, int nnz)
{
    __shared__ float s_pa[DF], s_pd[DF];
    if (threadIdx.x < DF) { s_pa[threadIdx.x] = 0.f; s_pd[threadIdx.x] = 0.f; }
    __syncthreads();

    float pa[DF], pd[DF];
#pragma unroll
    for (int k = 0; k < DF; k++) { pa[k] = 0.f; pd[k] = 0.f; }

    int tid = blockIdx.x * blockDim.x + threadIdx.x;
    int stride = gridDim.x * blockDim.x;
    for (int i = tid; i < nnz; i += stride) {
        int r = row[i], c = col[i];
        const float4* vp = (const float4*)(vals + (size_t)i * DF);
        float4 v0 = vp[0], v1 = vp[1], v2 = vp[2], v3 = vp[3];

        float* pr = &g_PrS[(size_t)r * DF];
        red4(pr + 0, v0); red4(pr + 4, v1); red4(pr + 8, v2); red4(pr + 12, v3);
        float* pc = &g_PcS[(size_t)c * DF];
        red4(pc + 0, v0); red4(pc + 4, v1); red4(pc + 8, v2); red4(pc + 12, v3);
        atomicAdd(&g_rcnt[r], 1);
        atomicAdd(&g_ccnt[c], 1);

        pa[0]  += v0.x; pa[1]  += v0.y; pa[2]  += v0.z; pa[3]  += v0.w;
        pa[4]  += v1.x; pa[5]  += v1.y; pa[6]  += v1.z; pa[7]  += v1.w;
        pa[8]  += v2.x; pa[9]  += v2.y; pa[10] += v2.z; pa[11] += v2.w;
        pa[12] += v3.x; pa[13] += v3.y; pa[14] += v3.z; pa[15] += v3.w;

        if (r == c) {
            float* dd = &g_D[(size_t)r * DF];
            red4(dd + 0, v0); red4(dd + 4, v1); red4(dd + 8, v2); red4(dd + 12, v3);
            pd[0]  += v0.x; pd[1]  += v0.y; pd[2]  += v0.z; pd[3]  += v0.w;
            pd[4]  += v1.x; pd[5]  += v1.y; pd[6]  += v1.z; pd[7]  += v1.w;
            pd[8]  += v2.x; pd[9]  += v2.y; pd[10] += v2.z; pd[11] += v2.w;
            pd[12] += v3.x; pd[13] += v3.y; pd[14] += v3.z; pd[15] += v3.w;
        }
    }

#pragma unroll
    for (int k = 0; k < DF; k++) {
#pragma unroll
        for (int o = 16; o > 0; o >>= 1) {
            pa[k] += __shfl_down_sync(0xffffffffu, pa[k], o);
            pd[k] += __shfl_down_sync(0xffffffffu, pd[k], o);
        }
    }
    if ((threadIdx.x & 31) == 0) {
#pragma unroll
        for (int k = 0; k < DF; k++) {
            atomicAdd(&s_pa[k], pa[k]);
            atomicAdd(&s_pd[k], pd[k]);
        }
    }
    __syncthreads();
    if (threadIdx.x < DF) {
        atomicAdd(&g_pasum[threadIdx.x], s_pa[threadIdx.x]);
        atomicAdd(&g_pdsum[threadIdx.x], s_pd[threadIdx.x]);
    }
}

// ---- K2: per-node broadcast vectors diag_b/row_b/col_b ----
__global__ void __launch_bounds__(256) k_node(const float* __restrict__ W) {
    __shared__ float sW[9 * DF * DF];  // W2..W10
    for (int t = threadIdx.x; t < 9 * DF * DF; t += blockDim.x)
        sW[t] = W[2 * DF * DF + t];
    __syncthreads();

    int gid = blockIdx.x * blockDim.x + threadIdx.x;
    int n = gid >> 2;
    int q = (gid & 3) * 4;
    if (n >= NN) return;

    float rinv = 1.f / (float)max(g_rcnt[n], 1);
    float cinv = 1.f / (float)max(g_ccnt[n], 1);

    float dv[DF], prv[DF], pcv[DF];
    {
        const float4* dp  = (const float4*)&g_D[(size_t)n * DF];
        const float4* prp = (const float4*)&g_PrS[(size_t)n * DF];
        const float4* pcp = (const float4*)&g_PcS[(size_t)n * DF];
        *(float4*)&dv[0]  = dp[0];  *(float4*)&dv[4]  = dp[1];
        *(float4*)&dv[8]  = dp[2];  *(float4*)&dv[12] = dp[3];
        *(float4*)&prv[0] = prp[0]; *(float4*)&prv[4] = prp[1];
        *(float4*)&prv[8] = prp[2]; *(float4*)&prv[12] = prp[3];
        *(float4*)&pcv[0] = pcp[0]; *(float4*)&pcv[4] = pcp[1];
        *(float4*)&pcv[8] = pcp[2]; *(float4*)&pcv[12] = pcp[3];
    }
#pragma unroll
    for (int k = 0; k < DF; k++) { prv[k] *= rinv; pcv[k] *= cinv; }

    float db[4], rb[4], cb[4];
#pragma unroll
    for (int t = 0; t < 4; t++) { db[t] = 0.f; rb[t] = 0.f; cb[t] = 0.f; }

#pragma unroll
    for (int j = 0; j < DF; j++) {
        float d = dv[j], pr = prv[j], pc = pcv[j];
        float4 w2 = *(const float4*)&sW[(0 * DF + j) * DF + q];
        float4 w3 = *(const float4*)&sW[(1 * DF + j) * DF + q];
        float4 w4 = *(const float4*)&sW[(2 * DF + j) * DF + q];
        float4 w5 = *(const float4*)&sW[(3 * DF + j) * DF + q];
        float4 w6 = *(const float4*)&sW[(4 * DF + j) * DF + q];
        float4 w7 = *(const float4*)&sW[(5 * DF + j) * DF + q];
        float4 w8 = *(const float4*)&sW[(6 * DF + j) * DF + q];
        float4 w9 = *(const float4*)&sW[(7 * DF + j) * DF + q];
        float4 wa = *(const float4*)&sW[(8 * DF + j) * DF + q];
        db[0] += d * w2.x + pr * w5.x + pc * w8.x;
        db[1] += d * w2.y + pr * w5.y + pc * w8.y;
        db[2] += d * w2.z + pr * w5.z + pc * w8.z;
        db[3] += d * w2.w + pr * w5.w + pc * w8.w;
        rb[0] += d * w3.x + pr * w6.x + pc * w9.x;
        rb[1] += d * w3.y + pr * w6.y + pc * w9.y;
        rb[2] += d * w3.z + pr * w6.z + pc * w9.z;
        rb[3] += d * w3.w + pr * w6.w + pc * w9.w;
        cb[0] += d * w4.x + pr * w7.x + pc * wa.x;
        cb[1] += d * w4.y + pr * w7.y + pc * wa.y;
        cb[2] += d * w4.z + pr * w7.z + pc * wa.z;
        cb[3] += d * w4.w + pr * w7.w + pc * wa.w;
    }

    *(float4*)&g_diagb[(size_t)n * DF + q] = make_float4(db[0], db[1], db[2], db[3]);
    *(float4*)&g_rowb[(size_t)n * DF + q]  = make_float4(rb[0], rb[1], rb[2], rb[3]);
    *(float4*)&g_colb[(size_t)n * DF + q]  = make_float4(cb[0], cb[1], cb[2], cb[3]);
}

// ---- K3: main per-entry pass, 4 lanes per entry (quad layout) ----
__global__ void __launch_bounds__(256) k_main(
    const float* __restrict__ vals, const int* __restrict__ row,
    const int* __restrict__ col, const float* __restrict__ W,
    const float* __restrict__ bias, float* __restrict__ Y, int nnz)
{
    __shared__ float sW0[DF * DF];
    __shared__ float scall[DF], scdiag[DF];
    sW0[threadIdx.x] = W[threadIdx.x];  // blockDim == 256
    if (threadIdx.x < DF) {
        int k = threadIdx.x;
        float inv_n = 1.f / (float)NN;
        float inv_e = 1.f / (float)nnz;
        float ds = 0.f, as = 0.f;
#pragma unroll
        for (int j = 0; j < DF; j++) {
            float pdj = g_pdsum[j] * inv_n;
            float paj = g_pasum[j] * inv_e;
            ds += pdj * W[11 * 256 + j * DF + k] + paj * W[13 * 256 + j * DF + k];
            as += pdj * W[12 * 256 + j * DF + k] + paj * W[14 * 256 + j * DF + k];
        }
        scall[k]  = as + bias[k];
        scdiag[k] = ds + bias[DF + k];
    }
    __syncthreads();

    int gid = blockIdx.x * blockDim.x + threadIdx.x;
    int e = gid >> 2;
    if (e >= nnz) return;
    int q = (gid & 3) * 4;
    unsigned gmask = 0xFu << ((threadIdx.x & 31) & 28);

    int r = row[e], c = col[e];

    float4 v4 = *(const float4*)(vals + (size_t)e * DF + q);
    float4 rb = *(const float4*)&g_rowb[(size_t)r * DF + q];
    float4 cb = *(const float4*)&g_colb[(size_t)c * DF + q];

    float y0 = scall[q + 0] + rb.x + cb.x;
    float y1 = scall[q + 1] + rb.y + cb.y;
    float y2 = scall[q + 2] + rb.z + cb.z;
    float y3 = scall[q + 3] + rb.w + cb.w;

    if (r == c) {
        float4 db = *(const float4*)&g_diagb[(size_t)r * DF + q];
        y0 += db.x + scdiag[q + 0];
        y1 += db.y + scdiag[q + 1];
        y2 += db.z + scdiag[q + 2];
        y3 += db.w + scdiag[q + 3];
    }

    // all-gather full v[16] across the 4-lane group
    float vf[DF];
#pragma unroll
    for (int s = 0; s < 4; s++) {
        vf[s * 4 + 0] = __shfl_sync(gmask, v4.x, s, 4);
        vf[s * 4 + 1] = __shfl_sync(gmask, v4.y, s, 4);
        vf[s * 4 + 2] = __shfl_sync(gmask, v4.z, s, 4);
        vf[s * 4 + 3] = __shfl_sync(gmask, v4.w, s, 4);
    }

#pragma unroll
    for (int j = 0; j < DF; j++) {
        float vj = vf[j];
        y0 += vj * sW0[j * DF + q + 0];
        y1 += vj * sW0[j * DF + q + 1];
        y2 += vj * sW0[j * DF + q + 2];
        y3 += vj * sW0[j * DF + q + 3];
    }

    *(float4*)(Y + (size_t)e * DF + q) = make_float4(y0, y1, y2, y3);
}

// ---- K4: transpose scatter-add, 4 lanes per transfer (quad layout) ----
__global__ void __launch_bounds__(256) k_trans(
    const float* __restrict__ vals, const int* __restrict__ tin,
    const int* __restrict__ tout, const float* __restrict__ W,
    float* __restrict__ Y, int nnzt)
{
    __shared__ float sW1[DF * DF];
    sW1[threadIdx.x] = W[DF * DF + threadIdx.x];  // W[1], blockDim == 256
    __syncthreads();

    int gid = blockIdx.x * blockDim.x + threadIdx.x;
    int t = gid >> 2;
    if (t >= nnzt) return;
    int q = (gid & 3) * 4;
    unsigned gmask = 0xFu << ((threadIdx.x & 31) & 28);

    int ii = tin[t], io = tout[t];

    float4 v4 = *(const float4*)(vals + (size_t)ii * DF + q);

    float vf[DF];
#pragma unroll
    for (int s = 0; s < 4; s++) {
        vf[s * 4 + 0] = __shfl_sync(gmask, v4.x, s, 4);
        vf[s * 4 + 1] = __shfl_sync(gmask, v4.y, s, 4);
        vf[s * 4 + 2] = __shfl_sync(gmask, v4.z, s, 4);
        vf[s * 4 + 3] = __shfl_sync(gmask, v4.w, s, 4);
    }

    float g0 = 0.f, g1 = 0.f, g2 = 0.f, g3 = 0.f;
#pragma unroll
    for (int j = 0; j < DF; j++) {
        float vj = vf[j];
        g0 += vj * sW1[j * DF + q + 0];
        g1 += vj * sW1[j * DF + q + 1];
        g2 += vj * sW1[j * DF + q + 2];
        g3 += vj * sW1[j * DF + q + 3];
    }

    red4(Y + (size_t)io * DF + q, make_float4(g0, g1, g2, g3));
}

extern "C" void kernel_launch(void* const* d_in, const int* in_sizes, int n_in,
                              void* d_out, int out_size) {
    const float* vals = (const float*)d_in[0];
    const float* W    = (const float*)d_in[1];
    const float* bias = (const float*)d_in[2];
    const int* row    = (const int*)d_in[3];
    const int* col    = (const int*)d_in[4];
    const int* tin    = (const int*)d_in[5];
    const int* tout   = (const int*)d_in[6];
    float* Y = (float*)d_out;

    int nnz  = in_sizes[0] / DF;
    int nnzt = in_sizes[5];

    k_zero<<<1024, 256>>>();
    k_pool<<<2368, 256>>>(vals, row, col, nnz);
    k_node<<<(NN * 4 + 255) / 256, 256>>>(W);
    k_main<<<(nnz * 4 + 255) / 256, 256>>>(vals, row, col, W, bias, Y, nnz);
    k_trans<<<(nnzt * 4 + 255) / 256, 256>>>(vals, tin, tout, W, Y, nnzt);
}

// round 5
// speedup vs baseline: 1.0328x; 1.0328x over previous
#include <cuda_runtime.h>

#define NN 100000
#define DF 16

// ---- device scratch (no allocations allowed) ----
__device__ float g_D[NN * DF];
__device__ float g_PrS[NN * DF];
__device__ float g_PcS[NN * DF];
__device__ int   g_rcnt[NN];
__device__ int   g_ccnt[NN];
__device__ float g_rowb[NN * DF];
__device__ float g_colb[NN * DF];
__device__ float g_diagb[NN * DF];
__device__ float g_pdsum[DF];
__device__ float g_pasum[DF];
__device__ float g_call[DF];   // all_scalar + bias[0]
__device__ float g_cdiag[DF];  // diag_scalar + bias[1]

__device__ __forceinline__ void red4(float* p, float4 v) {
    asm volatile("red.global.add.v4.f32 [%0], {%1,%2,%3,%4};"
                 :: "l"(p), "f"(v.x), "f"(v.y), "f"(v.z), "f"(v.w) : "memory");
}

// ---- K0: zero scratch (float4-vectorized) ----
__global__ void k_zero() {
    int tid = blockIdx.x * blockDim.x + threadIdx.x;
    int stride = gridDim.x * blockDim.x;
    float4 z = make_float4(0.f, 0.f, 0.f, 0.f);
    for (int t = tid; t < NN * DF / 4; t += stride) {
        ((float4*)g_PrS)[t] = z;
        ((float4*)g_PcS)[t] = z;
        ((float4*)g_D)[t]   = z;
    }
    for (int t = tid; t < NN; t += stride) { g_rcnt[t] = 0; g_ccnt[t] = 0; }
    if (blockIdx.x == 0 && threadIdx.x < DF) {
        g_pdsum[threadIdx.x] = 0.f; g_pasum[threadIdx.x] = 0.f;
    }
}

// ---- K1: pooling pass (segment sums + counts + global sums) ----
__global__ void __launch_bounds__(256) k_pool(
    const float* __restrict__ vals, const int* __restrict__ row,
    const int* __restrict__ col, int nnz)
{
    __shared__ float s_pa[DF], s_pd[DF];
    if (threadIdx.x < DF) { s_pa[threadIdx.x] = 0.f; s_pd[threadIdx.x] = 0.f; }
    __syncthreads();

    float pa[DF], pd[DF];
#pragma unroll
    for (int k = 0; k < DF; k++) { pa[k] = 0.f; pd[k] = 0.f; }

    int tid = blockIdx.x * blockDim.x + threadIdx.x;
    int stride = gridDim.x * blockDim.x;
    for (int i = tid; i < nnz; i += stride) {
        int r = row[i], c = col[i];
        const float4* vp = (const float4*)(vals + (size_t)i * DF);
        float4 v0 = vp[0], v1 = vp[1], v2 = vp[2], v3 = vp[3];

        float* pr = &g_PrS[(size_t)r * DF];
        red4(pr + 0, v0); red4(pr + 4, v1); red4(pr + 8, v2); red4(pr + 12, v3);
        float* pc = &g_PcS[(size_t)c * DF];
        red4(pc + 0, v0); red4(pc + 4, v1); red4(pc + 8, v2); red4(pc + 12, v3);
        atomicAdd(&g_rcnt[r], 1);
        atomicAdd(&g_ccnt[c], 1);

        pa[0]  += v0.x; pa[1]  += v0.y; pa[2]  += v0.z; pa[3]  += v0.w;
        pa[4]  += v1.x; pa[5]  += v1.y; pa[6]  += v1.z; pa[7]  += v1.w;
        pa[8]  += v2.x; pa[9]  += v2.y; pa[10] += v2.z; pa[11] += v2.w;
        pa[12] += v3.x; pa[13] += v3.y; pa[14] += v3.z; pa[15] += v3.w;

        if (r == c) {
            float* dd = &g_D[(size_t)r * DF];
            red4(dd + 0, v0); red4(dd + 4, v1); red4(dd + 8, v2); red4(dd + 12, v3);
            pd[0]  += v0.x; pd[1]  += v0.y; pd[2]  += v0.z; pd[3]  += v0.w;
            pd[4]  += v1.x; pd[5]  += v1.y; pd[6]  += v1.z; pd[7]  += v1.w;
            pd[8]  += v2.x; pd[9]  += v2.y; pd[10] += v2.z; pd[11] += v2.w;
            pd[12] += v3.x; pd[13] += v3.y; pd[14] += v3.z; pd[15] += v3.w;
        }
    }

#pragma unroll
    for (int k = 0; k < DF; k++) {
#pragma unroll
        for (int o = 16; o > 0; o >>= 1) {
            pa[k] += __shfl_down_sync(0xffffffffu, pa[k], o);
            pd[k] += __shfl_down_sync(0xffffffffu, pd[k], o);
        }
    }
    if ((threadIdx.x & 31) == 0) {
#pragma unroll
        for (int k = 0; k < DF; k++) {
            atomicAdd(&s_pa[k], pa[k]);
            atomicAdd(&s_pd[k], pd[k]);
        }
    }
    __syncthreads();
    if (threadIdx.x < DF) {
        atomicAdd(&g_pasum[threadIdx.x], s_pa[threadIdx.x]);
        atomicAdd(&g_pdsum[threadIdx.x], s_pd[threadIdx.x]);
    }
}

// ---- K2: per-node broadcast vectors + (block 0) scalar terms ----
__global__ void __launch_bounds__(256) k_node(const float* __restrict__ W,
                                              const float* __restrict__ bias,
                                              int nnz) {
    // block 0, threads 0-15 compute the scalar terms once
    if (blockIdx.x == 0 && threadIdx.x < DF) {
        int k = threadIdx.x;
        float inv_n = 1.f / (float)NN;
        float inv_e = 1.f / (float)nnz;
        float ds = 0.f, as = 0.f;
#pragma unroll
        for (int j = 0; j < DF; j++) {
            float pdj = g_pdsum[j] * inv_n;
            float paj = g_pasum[j] * inv_e;
            ds += pdj * W[11 * 256 + j * DF + k] + paj * W[13 * 256 + j * DF + k];
            as += pdj * W[12 * 256 + j * DF + k] + paj * W[14 * 256 + j * DF + k];
        }
        g_call[k]  = as + bias[k];
        g_cdiag[k] = ds + bias[DF + k];
    }

    __shared__ float sW[9 * DF * DF];  // W2..W10
    for (int t = threadIdx.x; t < 9 * DF * DF; t += blockDim.x)
        sW[t] = W[2 * DF * DF + t];
    __syncthreads();

    int gid = blockIdx.x * blockDim.x + threadIdx.x;
    int n = gid >> 2;
    int q = (gid & 3) * 4;
    if (n >= NN) return;

    float rinv = 1.f / (float)max(g_rcnt[n], 1);
    float cinv = 1.f / (float)max(g_ccnt[n], 1);

    float dv[DF], prv[DF], pcv[DF];
    {
        const float4* dp  = (const float4*)&g_D[(size_t)n * DF];
        const float4* prp = (const float4*)&g_PrS[(size_t)n * DF];
        const float4* pcp = (const float4*)&g_PcS[(size_t)n * DF];
        *(float4*)&dv[0]  = dp[0];  *(float4*)&dv[4]  = dp[1];
        *(float4*)&dv[8]  = dp[2];  *(float4*)&dv[12] = dp[3];
        *(float4*)&prv[0] = prp[0]; *(float4*)&prv[4] = prp[1];
        *(float4*)&prv[8] = prp[2]; *(float4*)&prv[12] = prp[3];
        *(float4*)&pcv[0] = pcp[0]; *(float4*)&pcv[4] = pcp[1];
        *(float4*)&pcv[8] = pcp[2]; *(float4*)&pcv[12] = pcp[3];
    }
#pragma unroll
    for (int k = 0; k < DF; k++) { prv[k] *= rinv; pcv[k] *= cinv; }

    float db[4], rb[4], cb[4];
#pragma unroll
    for (int t = 0; t < 4; t++) { db[t] = 0.f; rb[t] = 0.f; cb[t] = 0.f; }

#pragma unroll
    for (int j = 0; j < DF; j++) {
        float d = dv[j], pr = prv[j], pc = pcv[j];
        float4 w2 = *(const float4*)&sW[(0 * DF + j) * DF + q];
        float4 w3 = *(const float4*)&sW[(1 * DF + j) * DF + q];
        float4 w4 = *(const float4*)&sW[(2 * DF + j) * DF + q];
        float4 w5 = *(const float4*)&sW[(3 * DF + j) * DF + q];
        float4 w6 = *(const float4*)&sW[(4 * DF + j) * DF + q];
        float4 w7 = *(const float4*)&sW[(5 * DF + j) * DF + q];
        float4 w8 = *(const float4*)&sW[(6 * DF + j) * DF + q];
        float4 w9 = *(const float4*)&sW[(7 * DF + j) * DF + q];
        float4 wa = *(const float4*)&sW[(8 * DF + j) * DF + q];
        db[0] += d * w2.x + pr * w5.x + pc * w8.x;
        db[1] += d * w2.y + pr * w5.y + pc * w8.y;
        db[2] += d * w2.z + pr * w5.z + pc * w8.z;
        db[3] += d * w2.w + pr * w5.w + pc * w8.w;
        rb[0] += d * w3.x + pr * w6.x + pc * w9.x;
        rb[1] += d * w3.y + pr * w6.y + pc * w9.y;
        rb[2] += d * w3.z + pr * w6.z + pc * w9.z;
        rb[3] += d * w3.w + pr * w6.w + pc * w9.w;
        cb[0] += d * w4.x + pr * w7.x + pc * wa.x;
        cb[1] += d * w4.y + pr * w7.y + pc * wa.y;
        cb[2] += d * w4.z + pr * w7.z + pc * wa.z;
        cb[3] += d * w4.w + pr * w7.w + pc * wa.w;
    }

    *(float4*)&g_diagb[(size_t)n * DF + q] = make_float4(db[0], db[1], db[2], db[3]);
    *(float4*)&g_rowb[(size_t)n * DF + q]  = make_float4(rb[0], rb[1], rb[2], rb[3]);
    *(float4*)&g_colb[(size_t)n * DF + q]  = make_float4(cb[0], cb[1], cb[2], cb[3]);
}

// ---- helper: per-entry Y computation (entry-per-thread) ----
__device__ __forceinline__ void main_entry(
    int e, const float* __restrict__ vals, int r, int c,
    const float* sW0, const float* scall, const float* scdiag,
    float* __restrict__ Y)
{
    float v[DF];
    {
        const float4* vp = (const float4*)(vals + (size_t)e * DF);
        *(float4*)&v[0] = vp[0]; *(float4*)&v[4]  = vp[1];
        *(float4*)&v[8] = vp[2]; *(float4*)&v[12] = vp[3];
    }

    float y[DF];
    {
        const float4* rbp = (const float4*)&g_rowb[(size_t)r * DF];
        const float4* cbp = (const float4*)&g_colb[(size_t)c * DF];
        float rbv[DF], cbv[DF];
        *(float4*)&rbv[0] = rbp[0]; *(float4*)&rbv[4]  = rbp[1];
        *(float4*)&rbv[8] = rbp[2]; *(float4*)&rbv[12] = rbp[3];
        *(float4*)&cbv[0] = cbp[0]; *(float4*)&cbv[4]  = cbp[1];
        *(float4*)&cbv[8] = cbp[2]; *(float4*)&cbv[12] = cbp[3];
#pragma unroll
        for (int k = 0; k < DF; k++) y[k] = scall[k] + rbv[k] + cbv[k];
    }

    if (r == c) {
        const float4* dbp = (const float4*)&g_diagb[(size_t)r * DF];
        float dbv[DF];
        *(float4*)&dbv[0] = dbp[0]; *(float4*)&dbv[4]  = dbp[1];
        *(float4*)&dbv[8] = dbp[2]; *(float4*)&dbv[12] = dbp[3];
#pragma unroll
        for (int k = 0; k < DF; k++) y[k] += dbv[k] + scdiag[k];
    }

#pragma unroll
    for (int j = 0; j < DF; j++) {
        float vj = v[j];
#pragma unroll
        for (int k = 0; k < DF; k++) y[k] += vj * sW0[j * DF + k];
    }

    float4* yo = (float4*)(Y + (size_t)e * DF);
    yo[0] = *(float4*)&y[0]; yo[1] = *(float4*)&y[4];
    yo[2] = *(float4*)&y[8]; yo[3] = *(float4*)&y[12];
}

// ---- K3: main per-entry pass, 2 entries per thread for MLP ----
__global__ void __launch_bounds__(256) k_main(
    const float* __restrict__ vals, const int* __restrict__ row,
    const int* __restrict__ col, const float* __restrict__ W,
    float* __restrict__ Y, int nnz)
{
    __shared__ float sW0[DF * DF];
    __shared__ float scall[DF], scdiag[DF];
    sW0[threadIdx.x] = W[threadIdx.x];  // blockDim == 256
    if (threadIdx.x < DF) {
        scall[threadIdx.x]  = g_call[threadIdx.x];
        scdiag[threadIdx.x] = g_cdiag[threadIdx.x];
    }
    __syncthreads();

    int e0 = blockIdx.x * 512 + threadIdx.x;
    int e1 = e0 + 256;
    if (e0 >= nnz) return;

    // front-batch both index loads (independent chains -> high MLP)
    int r0 = row[e0], c0 = col[e0];
    int r1 = 0, c1 = 0;
    bool p1 = e1 < nnz;
    if (p1) { r1 = row[e1]; c1 = col[e1]; }

    main_entry(e0, vals, r0, c0, sW0, scall, scdiag, Y);
    if (p1) main_entry(e1, vals, r1, c1, sW0, scall, scdiag, Y);
}

// ---- K4: transpose scatter-add (entry per thread) ----
__global__ void __launch_bounds__(256) k_trans(
    const float* __restrict__ vals, const int* __restrict__ tin,
    const int* __restrict__ tout, const float* __restrict__ W,
    float* __restrict__ Y, int nnzt)
{
    __shared__ float sW1[DF * DF];
    sW1[threadIdx.x] = W[DF * DF + threadIdx.x];  // W[1], blockDim == 256
    __syncthreads();

    int t = blockIdx.x * blockDim.x + threadIdx.x;
    if (t >= nnzt) return;

    int ii = tin[t], io = tout[t];

    float v[DF];
    {
        const float4* vp = (const float4*)(vals + (size_t)ii * DF);
        *(float4*)&v[0] = vp[0]; *(float4*)&v[4]  = vp[1];
        *(float4*)&v[8] = vp[2]; *(float4*)&v[12] = vp[3];
    }

    float g[DF];
#pragma unroll
    for (int k = 0; k < DF; k++) g[k] = 0.f;
#pragma unroll
    for (int j = 0; j < DF; j++) {
        float vj = v[j];
#pragma unroll
        for (int k = 0; k < DF; k++) g[k] += vj * sW1[j * DF + k];
    }

    float* yp = Y + (size_t)io * DF;
    red4(yp + 0,  make_float4(g[0],  g[1],  g[2],  g[3]));
    red4(yp + 4,  make_float4(g[4],  g[5],  g[6],  g[7]));
    red4(yp + 8,  make_float4(g[8],  g[9],  g[10], g[11]));
    red4(yp + 12, make_float4(g[12], g[13], g[14], g[15]));
}

extern "C" void kernel_launch(void* const* d_in, const int* in_sizes, int n_in,
                              void* d_out, int out_size) {
    const float* vals = (const float*)d_in[0];
    const float* W    = (const float*)d_in[1];
    const float* bias = (const float*)d_in[2];
    const int* row    = (const int*)d_in[3];
    const int* col    = (const int*)d_in[4];
    const int* tin    = (const int*)d_in[5];
    const int* tout   = (const int*)d_in[6];
    float* Y = (float*)d_out;

    int nnz  = in_sizes[0] / DF;
    int nnzt = in_sizes[5];

    k_zero<<<1024, 256>>>();
    k_pool<<<2368, 256>>>(vals, row, col, nnz);
    k_node<<<(NN * 4 + 255) / 256, 256>>>(W, bias, nnz);
    k_main<<<(nnz + 511) / 512, 256>>>(vals, row, col, W, Y, nnz);
    k_trans<<<(nnzt + 255) / 256, 256>>>(vals, tin, tout, W, Y, nnzt);
}

// round 6
// speedup vs baseline: 1.1960x; 1.1580x over previous
#include <cuda_runtime.h>
#include <cuda_fp16.h>

#define NN 100000
#define DF 16

// ---- device scratch (no allocations allowed) ----
__device__ float g_D[NN * DF];
__device__ float g_PrS[NN * DF];
__device__ float g_PcS[NN * DF];
__device__ int   g_rcnt[NN];
__device__ int   g_ccnt[NN];
// fp16 broadcast tables: 16 halves (32B) per node
__device__ __align__(16) __half2 g_rowb_h[NN * 8];
__device__ __align__(16) __half2 g_colb_h[NN * 8];
__device__ __align__(16) __half2 g_diagb_h[NN * 8];
__device__ float g_pdsum[DF];
__device__ float g_pasum[DF];
__device__ float g_call[DF];   // all_scalar + bias[0]
__device__ float g_cdiag[DF];  // diag_scalar + bias[1]

__device__ __forceinline__ void red4(float* p, float4 v) {
    asm volatile("red.global.add.v4.f32 [%0], {%1,%2,%3,%4};"
                 :: "l"(p), "f"(v.x), "f"(v.y), "f"(v.z), "f"(v.w) : "memory");
}

// ---- K0: zero scratch (float4-vectorized) ----
__global__ void k_zero() {
    int tid = blockIdx.x * blockDim.x + threadIdx.x;
    int stride = gridDim.x * blockDim.x;
    float4 z = make_float4(0.f, 0.f, 0.f, 0.f);
    for (int t = tid; t < NN * DF / 4; t += stride) {
        ((float4*)g_PrS)[t] = z;
        ((float4*)g_PcS)[t] = z;
        ((float4*)g_D)[t]   = z;
    }
    for (int t = tid; t < NN; t += stride) { g_rcnt[t] = 0; g_ccnt[t] = 0; }
    if (blockIdx.x == 0 && threadIdx.x < DF) {
        g_pdsum[threadIdx.x] = 0.f; g_pasum[threadIdx.x] = 0.f;
    }
}

// ---- K1: pooling pass (segment sums + counts + global sums) ----
__global__ void __launch_bounds__(256) k_pool(
    const float* __restrict__ vals, const int* __restrict__ row,
    const int* __restrict__ col, int nnz)
{
    __shared__ float s_pa[DF], s_pd[DF];
    if (threadIdx.x < DF) { s_pa[threadIdx.x] = 0.f; s_pd[threadIdx.x] = 0.f; }
    __syncthreads();

    float pa[DF], pd[DF];
#pragma unroll
    for (int k = 0; k < DF; k++) { pa[k] = 0.f; pd[k] = 0.f; }

    int tid = blockIdx.x * blockDim.x + threadIdx.x;
    int stride = gridDim.x * blockDim.x;
    for (int i = tid; i < nnz; i += stride) {
        int r = row[i], c = col[i];
        const float4* vp = (const float4*)(vals + (size_t)i * DF);
        float4 v0 = vp[0], v1 = vp[1], v2 = vp[2], v3 = vp[3];

        float* pr = &g_PrS[(size_t)r * DF];
        red4(pr + 0, v0); red4(pr + 4, v1); red4(pr + 8, v2); red4(pr + 12, v3);
        float* pc = &g_PcS[(size_t)c * DF];
        red4(pc + 0, v0); red4(pc + 4, v1); red4(pc + 8, v2); red4(pc + 12, v3);
        atomicAdd(&g_rcnt[r], 1);
        atomicAdd(&g_ccnt[c], 1);

        pa[0]  += v0.x; pa[1]  += v0.y; pa[2]  += v0.z; pa[3]  += v0.w;
        pa[4]  += v1.x; pa[5]  += v1.y; pa[6]  += v1.z; pa[7]  += v1.w;
        pa[8]  += v2.x; pa[9]  += v2.y; pa[10] += v2.z; pa[11] += v2.w;
        pa[12] += v3.x; pa[13] += v3.y; pa[14] += v3.z; pa[15] += v3.w;

        if (r == c) {
            float* dd = &g_D[(size_t)r * DF];
            red4(dd + 0, v0); red4(dd + 4, v1); red4(dd + 8, v2); red4(dd + 12, v3);
            pd[0]  += v0.x; pd[1]  += v0.y; pd[2]  += v0.z; pd[3]  += v0.w;
            pd[4]  += v1.x; pd[5]  += v1.y; pd[6]  += v1.z; pd[7]  += v1.w;
            pd[8]  += v2.x; pd[9]  += v2.y; pd[10] += v2.z; pd[11] += v2.w;
            pd[12] += v3.x; pd[13] += v3.y; pd[14] += v3.z; pd[15] += v3.w;
        }
    }

#pragma unroll
    for (int k = 0; k < DF; k++) {
#pragma unroll
        for (int o = 16; o > 0; o >>= 1) {
            pa[k] += __shfl_down_sync(0xffffffffu, pa[k], o);
            pd[k] += __shfl_down_sync(0xffffffffu, pd[k], o);
        }
    }
    if ((threadIdx.x & 31) == 0) {
#pragma unroll
        for (int k = 0; k < DF; k++) {
            atomicAdd(&s_pa[k], pa[k]);
            atomicAdd(&s_pd[k], pd[k]);
        }
    }
    __syncthreads();
    if (threadIdx.x < DF) {
        atomicAdd(&g_pasum[threadIdx.x], s_pa[threadIdx.x]);
        atomicAdd(&g_pdsum[threadIdx.x], s_pd[threadIdx.x]);
    }
}

// ---- K2: per-node broadcast vectors (fp16 out) + (block 0) scalar terms ----
__global__ void __launch_bounds__(256) k_node(const float* __restrict__ W,
                                              const float* __restrict__ bias,
                                              int nnz) {
    if (blockIdx.x == 0 && threadIdx.x < DF) {
        int k = threadIdx.x;
        float inv_n = 1.f / (float)NN;
        float inv_e = 1.f / (float)nnz;
        float ds = 0.f, as = 0.f;
#pragma unroll
        for (int j = 0; j < DF; j++) {
            float pdj = g_pdsum[j] * inv_n;
            float paj = g_pasum[j] * inv_e;
            ds += pdj * W[11 * 256 + j * DF + k] + paj * W[13 * 256 + j * DF + k];
            as += pdj * W[12 * 256 + j * DF + k] + paj * W[14 * 256 + j * DF + k];
        }
        g_call[k]  = as + bias[k];
        g_cdiag[k] = ds + bias[DF + k];
    }

    __shared__ float sW[9 * DF * DF];  // W2..W10
    for (int t = threadIdx.x; t < 9 * DF * DF; t += blockDim.x)
        sW[t] = W[2 * DF * DF + t];
    __syncthreads();

    int gid = blockIdx.x * blockDim.x + threadIdx.x;
    int n = gid >> 2;
    int q = (gid & 3) * 4;
    if (n >= NN) return;

    float rinv = 1.f / (float)max(g_rcnt[n], 1);
    float cinv = 1.f / (float)max(g_ccnt[n], 1);

    float dv[DF], prv[DF], pcv[DF];
    {
        const float4* dp  = (const float4*)&g_D[(size_t)n * DF];
        const float4* prp = (const float4*)&g_PrS[(size_t)n * DF];
        const float4* pcp = (const float4*)&g_PcS[(size_t)n * DF];
        *(float4*)&dv[0]  = dp[0];  *(float4*)&dv[4]  = dp[1];
        *(float4*)&dv[8]  = dp[2];  *(float4*)&dv[12] = dp[3];
        *(float4*)&prv[0] = prp[0]; *(float4*)&prv[4] = prp[1];
        *(float4*)&prv[8] = prp[2]; *(float4*)&prv[12] = prp[3];
        *(float4*)&pcv[0] = pcp[0]; *(float4*)&pcv[4] = pcp[1];
        *(float4*)&pcv[8] = pcp[2]; *(float4*)&pcv[12] = pcp[3];
    }
#pragma unroll
    for (int k = 0; k < DF; k++) { prv[k] *= rinv; pcv[k] *= cinv; }

    float db[4], rb[4], cb[4];
#pragma unroll
    for (int t = 0; t < 4; t++) { db[t] = 0.f; rb[t] = 0.f; cb[t] = 0.f; }

#pragma unroll
    for (int j = 0; j < DF; j++) {
        float d = dv[j], pr = prv[j], pc = pcv[j];
        float4 w2 = *(const float4*)&sW[(0 * DF + j) * DF + q];
        float4 w3 = *(const float4*)&sW[(1 * DF + j) * DF + q];
        float4 w4 = *(const float4*)&sW[(2 * DF + j) * DF + q];
        float4 w5 = *(const float4*)&sW[(3 * DF + j) * DF + q];
        float4 w6 = *(const float4*)&sW[(4 * DF + j) * DF + q];
        float4 w7 = *(const float4*)&sW[(5 * DF + j) * DF + q];
        float4 w8 = *(const float4*)&sW[(6 * DF + j) * DF + q];
        float4 w9 = *(const float4*)&sW[(7 * DF + j) * DF + q];
        float4 wa = *(const float4*)&sW[(8 * DF + j) * DF + q];
        db[0] += d * w2.x + pr * w5.x + pc * w8.x;
        db[1] += d * w2.y + pr * w5.y + pc * w8.y;
        db[2] += d * w2.z + pr * w5.z + pc * w8.z;
        db[3] += d * w2.w + pr * w5.w + pc * w8.w;
        rb[0] += d * w3.x + pr * w6.x + pc * w9.x;
        rb[1] += d * w3.y + pr * w6.y + pc * w9.y;
        rb[2] += d * w3.z + pr * w6.z + pc * w9.z;
        rb[3] += d * w3.w + pr * w6.w + pc * w9.w;
        cb[0] += d * w4.x + pr * w7.x + pc * wa.x;
        cb[1] += d * w4.y + pr * w7.y + pc * wa.y;
        cb[2] += d * w4.z + pr * w7.z + pc * wa.z;
        cb[3] += d * w4.w + pr * w7.w + pc * wa.w;
    }

    // store as fp16: 4 floats -> 2 half2 -> 8B per table
    int hidx = n * 8 + (q >> 1);
    __half2 d0 = __floats2half2_rn(db[0], db[1]);
    __half2 d1 = __floats2half2_rn(db[2], db[3]);
    __half2 r0 = __floats2half2_rn(rb[0], rb[1]);
    __half2 r1 = __floats2half2_rn(rb[2], rb[3]);
    __half2 c0 = __floats2half2_rn(cb[0], cb[1]);
    __half2 c1 = __floats2half2_rn(cb[2], cb[3]);
    *(uint2*)&g_diagb_h[hidx] = make_uint2(*(unsigned*)&d0, *(unsigned*)&d1);
    *(uint2*)&g_rowb_h[hidx]  = make_uint2(*(unsigned*)&r0, *(unsigned*)&r1);
    *(uint2*)&g_colb_h[hidx]  = make_uint2(*(unsigned*)&c0, *(unsigned*)&c1);
}

// unpack 16 halves (loaded as 2x uint4) into float dst[16], added into y
__device__ __forceinline__ void add_h16(float* y, uint4 u0, uint4 u1) {
    const unsigned* u = &u0.x;
#pragma unroll
    for (int p = 0; p < 4; p++) {
        float2 f = __half22float2(*(const __half2*)&u[p]);
        y[p * 2 + 0] += f.x; y[p * 2 + 1] += f.y;
    }
    const unsigned* w = &u1.x;
#pragma unroll
    for (int p = 0; p < 4; p++) {
        float2 f = __half22float2(*(const __half2*)&w[p]);
        y[8 + p * 2 + 0] += f.x; y[8 + p * 2 + 1] += f.y;
    }
}

// ---- K3: main per-entry pass (entry-per-thread, fp16 gathers) ----
__global__ void __launch_bounds__(256) k_main(
    const float* __restrict__ vals, const int* __restrict__ row,
    const int* __restrict__ col, const float* __restrict__ W,
    float* __restrict__ Y, int nnz)
{
    __shared__ float sW0[DF * DF];
    __shared__ float scall[DF], scdiag[DF];
    sW0[threadIdx.x] = W[threadIdx.x];  // blockDim == 256
    if (threadIdx.x < DF) {
        scall[threadIdx.x]  = g_call[threadIdx.x];
        scdiag[threadIdx.x] = g_cdiag[threadIdx.x];
    }
    __syncthreads();

    int i = blockIdx.x * blockDim.x + threadIdx.x;
    if (i >= nnz) return;

    int r = row[i], c = col[i];

    // front-batch all loads: vals (4x LDG.128) + rowb (2x) + colb (2x)
    float v[DF];
    {
        const float4* vp = (const float4*)(vals + (size_t)i * DF);
        *(float4*)&v[0] = vp[0]; *(float4*)&v[4]  = vp[1];
        *(float4*)&v[8] = vp[2]; *(float4*)&v[12] = vp[3];
    }
    const uint4* rbp = (const uint4*)&g_rowb_h[(size_t)r * 8];
    const uint4* cbp = (const uint4*)&g_colb_h[(size_t)c * 8];
    uint4 rb0 = rbp[0], rb1 = rbp[1];
    uint4 cb0 = cbp[0], cb1 = cbp[1];

    float y[DF];
#pragma unroll
    for (int k = 0; k < DF; k++) y[k] = scall[k];
    add_h16(y, rb0, rb1);
    add_h16(y, cb0, cb1);

    if (r == c) {
        const uint4* dbp = (const uint4*)&g_diagb_h[(size_t)r * 8];
        uint4 db0 = dbp[0], db1 = dbp[1];
        add_h16(y, db0, db1);
#pragma unroll
        for (int k = 0; k < DF; k++) y[k] += scdiag[k];
    }

#pragma unroll
    for (int j = 0; j < DF; j++) {
        float vj = v[j];
#pragma unroll
        for (int k = 0; k < DF; k++) y[k] += vj * sW0[j * DF + k];
    }

    float4* yo = (float4*)(Y + (size_t)i * DF);
    yo[0] = *(float4*)&y[0]; yo[1] = *(float4*)&y[4];
    yo[2] = *(float4*)&y[8]; yo[3] = *(float4*)&y[12];
}

// ---- K4: transpose scatter-add (entry per thread) ----
__global__ void __launch_bounds__(256) k_trans(
    const float* __restrict__ vals, const int* __restrict__ tin,
    const int* __restrict__ tout, const float* __restrict__ W,
    float* __restrict__ Y, int nnzt)
{
    __shared__ float sW1[DF * DF];
    sW1[threadIdx.x] = W[DF * DF + threadIdx.x];  // W[1], blockDim == 256
    __syncthreads();

    int t = blockIdx.x * blockDim.x + threadIdx.x;
    if (t >= nnzt) return;

    int ii = tin[t], io = tout[t];

    float v[DF];
    {
        const float4* vp = (const float4*)(vals + (size_t)ii * DF);
        *(float4*)&v[0] = vp[0]; *(float4*)&v[4]  = vp[1];
        *(float4*)&v[8] = vp[2]; *(float4*)&v[12] = vp[3];
    }

    float g[DF];
#pragma unroll
    for (int k = 0; k < DF; k++) g[k] = 0.f;
#pragma unroll
    for (int j = 0; j < DF; j++) {
        float vj = v[j];
#pragma unroll
        for (int k = 0; k < DF; k++) g[k] += vj * sW1[j * DF + k];
    }

    float* yp = Y + (size_t)io * DF;
    red4(yp + 0,  make_float4(g[0],  g[1],  g[2],  g[3]));
    red4(yp + 4,  make_float4(g[4],  g[5],  g[6],  g[7]));
    red4(yp + 8,  make_float4(g[8],  g[9],  g[10], g[11]));
    red4(yp + 12, make_float4(g[12], g[13], g[14], g[15]));
}

extern "C" void kernel_launch(void* const* d_in, const int* in_sizes, int n_in,
                              void* d_out, int out_size) {
    const float* vals = (const float*)d_in[0];
    const float* W    = (const float*)d_in[1];
    const float* bias = (const float*)d_in[2];
    const int* row    = (const int*)d_in[3];
    const int* col    = (const int*)d_in[4];
    const int* tin    = (const int*)d_in[5];
    const int* tout   = (const int*)d_in[6];
    float* Y = (float*)d_out;

    int nnz  = in_sizes[0] / DF;
    int nnzt = in_sizes[5];

    k_zero<<<1024, 256>>>();
    k_pool<<<2368, 256>>>(vals, row, col, nnz);
    k_node<<<(NN * 4 + 255) / 256, 256>>>(W, bias, nnz);
    k_main<<<(nnz + 255) / 256, 256>>>(vals, row, col, W, Y, nnz);
    k_trans<<<(nnzt + 255) / 256, 256>>>(vals, tin, tout, W, Y, nnzt);
}

// round 7
// speedup vs baseline: 1.5067x; 1.2598x over previous
#include <cuda_runtime.h>
#include <cuda_fp16.h>

#define NN 100000
#define DF 16

// ---- device scratch (no allocations allowed) ----
__device__ float g_D[NN * DF];                      // diag sums, fp32 (rarely hit)
__device__ __align__(16) __half2 g_PrS_h[NN * 8];   // row sums, fp16 (32B/node)
__device__ __align__(16) __half2 g_PcS_h[NN * 8];   // col sums, fp16
__device__ int   g_rcnt[NN];
__device__ int   g_ccnt[NN];
// fp16 broadcast tables: 16 halves (32B) per node
__device__ __align__(16) __half2 g_rowb_h[NN * 8];
__device__ __align__(16) __half2 g_colb_h[NN * 8];
__device__ __align__(16) __half2 g_diagb_h[NN * 8];
__device__ float g_pdsum[DF];
__device__ float g_pasum[DF];
__device__ float g_call[DF];   // all_scalar + bias[0]
__device__ float g_cdiag[DF];  // diag_scalar + bias[1]

__device__ __forceinline__ void red4(float* p, float4 v) {
    asm volatile("red.global.add.v4.f32 [%0], {%1,%2,%3,%4};"
                 :: "l"(p), "f"(v.x), "f"(v.y), "f"(v.z), "f"(v.w) : "memory");
}
__device__ __forceinline__ void red4h(__half2* p, unsigned a, unsigned b,
                                      unsigned c, unsigned d) {
    asm volatile("red.global.add.noftz.v4.f16x2 [%0], {%1,%2,%3,%4};"
                 :: "l"(p), "r"(a), "r"(b), "r"(c), "r"(d) : "memory");
}

// ---- K0: zero scratch ----
__global__ void k_zero() {
    int tid = blockIdx.x * blockDim.x + threadIdx.x;
    int stride = gridDim.x * blockDim.x;
    float4 z = make_float4(0.f, 0.f, 0.f, 0.f);
    uint4 zu = make_uint4(0, 0, 0, 0);
    for (int t = tid; t < NN * 4; t += stride) ((float4*)g_D)[t] = z;
    for (int t = tid; t < NN * 2; t += stride) {
        ((uint4*)g_PrS_h)[t] = zu;
        ((uint4*)g_PcS_h)[t] = zu;
    }
    for (int t = tid; t < NN; t += stride) { g_rcnt[t] = 0; g_ccnt[t] = 0; }
    if (blockIdx.x == 0 && threadIdx.x < DF) {
        g_pdsum[threadIdx.x] = 0.f; g_pasum[threadIdx.x] = 0.f;
    }
}

// ---- K1: pooling pass (fp16 vector REDs for Pr/Pc) ----
__global__ void __launch_bounds__(256) k_pool(
    const float* __restrict__ vals, const int* __restrict__ row,
    const int* __restrict__ col, int nnz)
{
    __shared__ float s_pa[DF], s_pd[DF];
    if (threadIdx.x < DF) { s_pa[threadIdx.x] = 0.f; s_pd[threadIdx.x] = 0.f; }
    __syncthreads();

    float pa[DF], pd[DF];
#pragma unroll
    for (int k = 0; k < DF; k++) { pa[k] = 0.f; pd[k] = 0.f; }

    int tid = blockIdx.x * blockDim.x + threadIdx.x;
    int stride = gridDim.x * blockDim.x;
    for (int i = tid; i < nnz; i += stride) {
        int r = row[i], c = col[i];
        const float4* vp = (const float4*)(vals + (size_t)i * DF);
        float4 v0 = vp[0], v1 = vp[1], v2 = vp[2], v3 = vp[3];

        // pack 16 floats -> 8 half2 once, reuse for both tables
        __half2 hv[8];
        hv[0] = __floats2half2_rn(v0.x, v0.y); hv[1] = __floats2half2_rn(v0.z, v0.w);
        hv[2] = __floats2half2_rn(v1.x, v1.y); hv[3] = __floats2half2_rn(v1.z, v1.w);
        hv[4] = __floats2half2_rn(v2.x, v2.y); hv[5] = __floats2half2_rn(v2.z, v2.w);
        hv[6] = __floats2half2_rn(v3.x, v3.y); hv[7] = __floats2half2_rn(v3.z, v3.w);
        const unsigned* hu = (const unsigned*)hv;

        __half2* pr = g_PrS_h + (size_t)r * 8;
        red4h(pr + 0, hu[0], hu[1], hu[2], hu[3]);
        red4h(pr + 4, hu[4], hu[5], hu[6], hu[7]);
        __half2* pc = g_PcS_h + (size_t)c * 8;
        red4h(pc + 0, hu[0], hu[1], hu[2], hu[3]);
        red4h(pc + 4, hu[4], hu[5], hu[6], hu[7]);
        atomicAdd(&g_rcnt[r], 1);
        atomicAdd(&g_ccnt[c], 1);

        pa[0]  += v0.x; pa[1]  += v0.y; pa[2]  += v0.z; pa[3]  += v0.w;
        pa[4]  += v1.x; pa[5]  += v1.y; pa[6]  += v1.z; pa[7]  += v1.w;
        pa[8]  += v2.x; pa[9]  += v2.y; pa[10] += v2.z; pa[11] += v2.w;
        pa[12] += v3.x; pa[13] += v3.y; pa[14] += v3.z; pa[15] += v3.w;

        if (r == c) {
            float* dd = &g_D[(size_t)r * DF];
            red4(dd + 0, v0); red4(dd + 4, v1); red4(dd + 8, v2); red4(dd + 12, v3);
            pd[0]  += v0.x; pd[1]  += v0.y; pd[2]  += v0.z; pd[3]  += v0.w;
            pd[4]  += v1.x; pd[5]  += v1.y; pd[6]  += v1.z; pd[7]  += v1.w;
            pd[8]  += v2.x; pd[9]  += v2.y; pd[10] += v2.z; pd[11] += v2.w;
            pd[12] += v3.x; pd[13] += v3.y; pd[14] += v3.z; pd[15] += v3.w;
        }
    }

#pragma unroll
    for (int k = 0; k < DF; k++) {
#pragma unroll
        for (int o = 16; o > 0; o >>= 1) {
            pa[k] += __shfl_down_sync(0xffffffffu, pa[k], o);
            pd[k] += __shfl_down_sync(0xffffffffu, pd[k], o);
        }
    }
    if ((threadIdx.x & 31) == 0) {
#pragma unroll
        for (int k = 0; k < DF; k++) {
            atomicAdd(&s_pa[k], pa[k]);
            atomicAdd(&s_pd[k], pd[k]);
        }
    }
    __syncthreads();
    if (threadIdx.x < DF) {
        atomicAdd(&g_pasum[threadIdx.x], s_pa[threadIdx.x]);
        atomicAdd(&g_pdsum[threadIdx.x], s_pd[threadIdx.x]);
    }
}

// unpack a uint4 (8 halves) into f[8]
__device__ __forceinline__ void h8_to_f(const uint4& u, float* f) {
    const unsigned* p = &u.x;
#pragma unroll
    for (int i = 0; i < 4; i++) {
        float2 t = __half22float2(*(const __half2*)&p[i]);
        f[i * 2 + 0] = t.x; f[i * 2 + 1] = t.y;
    }
}

// ---- K2: per-node broadcast vectors (fp16 in/out) + (block 0) scalars ----
__global__ void __launch_bounds__(256) k_node(const float* __restrict__ W,
                                              const float* __restrict__ bias,
                                              int nnz) {
    if (blockIdx.x == 0 && threadIdx.x < DF) {
        int k = threadIdx.x;
        float inv_n = 1.f / (float)NN;
        float inv_e = 1.f / (float)nnz;
        float ds = 0.f, as = 0.f;
#pragma unroll
        for (int j = 0; j < DF; j++) {
            float pdj = g_pdsum[j] * inv_n;
            float paj = g_pasum[j] * inv_e;
            ds += pdj * W[11 * 256 + j * DF + k] + paj * W[13 * 256 + j * DF + k];
            as += pdj * W[12 * 256 + j * DF + k] + paj * W[14 * 256 + j * DF + k];
        }
        g_call[k]  = as + bias[k];
        g_cdiag[k] = ds + bias[DF + k];
    }

    __shared__ float sW[9 * DF * DF];  // W2..W10
    for (int t = threadIdx.x; t < 9 * DF * DF; t += blockDim.x)
        sW[t] = W[2 * DF * DF + t];
    __syncthreads();

    int gid = blockIdx.x * blockDim.x + threadIdx.x;
    int n = gid >> 2;
    int q = (gid & 3) * 4;
    if (n >= NN) return;

    float rinv = 1.f / (float)max(g_rcnt[n], 1);
    float cinv = 1.f / (float)max(g_ccnt[n], 1);

    float dv[DF], prv[DF], pcv[DF];
    {
        const float4* dp  = (const float4*)&g_D[(size_t)n * DF];
        *(float4*)&dv[0]  = dp[0];  *(float4*)&dv[4]  = dp[1];
        *(float4*)&dv[8]  = dp[2];  *(float4*)&dv[12] = dp[3];
        const uint4* prp = (const uint4*)(g_PrS_h + (size_t)n * 8);
        const uint4* pcp = (const uint4*)(g_PcS_h + (size_t)n * 8);
        uint4 a = prp[0], b = prp[1], cgl = pcp[0], d = pcp[1];
        h8_to_f(a, &prv[0]); h8_to_f(b, &prv[8]);
        h8_to_f(cgl, &pcv[0]); h8_to_f(d, &pcv[8]);
    }
#pragma unroll
    for (int k = 0; k < DF; k++) { prv[k] *= rinv; pcv[k] *= cinv; }

    float db[4], rb[4], cb[4];
#pragma unroll
    for (int t = 0; t < 4; t++) { db[t] = 0.f; rb[t] = 0.f; cb[t] = 0.f; }

#pragma unroll
    for (int j = 0; j < DF; j++) {
        float d = dv[j], pr = prv[j], pc = pcv[j];
        float4 w2 = *(const float4*)&sW[(0 * DF + j) * DF + q];
        float4 w3 = *(const float4*)&sW[(1 * DF + j) * DF + q];
        float4 w4 = *(const float4*)&sW[(2 * DF + j) * DF + q];
        float4 w5 = *(const float4*)&sW[(3 * DF + j) * DF + q];
        float4 w6 = *(const float4*)&sW[(4 * DF + j) * DF + q];
        float4 w7 = *(const float4*)&sW[(5 * DF + j) * DF + q];
        float4 w8 = *(const float4*)&sW[(6 * DF + j) * DF + q];
        float4 w9 = *(const float4*)&sW[(7 * DF + j) * DF + q];
        float4 wa = *(const float4*)&sW[(8 * DF + j) * DF + q];
        db[0] += d * w2.x + pr * w5.x + pc * w8.x;
        db[1] += d * w2.y + pr * w5.y + pc * w8.y;
        db[2] += d * w2.z + pr * w5.z + pc * w8.z;
        db[3] += d * w2.w + pr * w5.w + pc * w8.w;
        rb[0] += d * w3.x + pr * w6.x + pc * w9.x;
        rb[1] += d * w3.y + pr * w6.y + pc * w9.y;
        rb[2] += d * w3.z + pr * w6.z + pc * w9.z;
        rb[3] += d * w3.w + pr * w6.w + pc * w9.w;
        cb[0] += d * w4.x + pr * w7.x + pc * wa.x;
        cb[1] += d * w4.y + pr * w7.y + pc * wa.y;
        cb[2] += d * w4.z + pr * w7.z + pc * wa.z;
        cb[3] += d * w4.w + pr * w7.w + pc * wa.w;
    }

    int hidx = n * 8 + (q >> 1);
    __half2 d0 = __floats2half2_rn(db[0], db[1]);
    __half2 d1 = __floats2half2_rn(db[2], db[3]);
    __half2 r0 = __floats2half2_rn(rb[0], rb[1]);
    __half2 r1 = __floats2half2_rn(rb[2], rb[3]);
    __half2 c0 = __floats2half2_rn(cb[0], cb[1]);
    __half2 c1 = __floats2half2_rn(cb[2], cb[3]);
    *(uint2*)&g_diagb_h[hidx] = make_uint2(*(unsigned*)&d0, *(unsigned*)&d1);
    *(uint2*)&g_rowb_h[hidx]  = make_uint2(*(unsigned*)&r0, *(unsigned*)&r1);
    *(uint2*)&g_colb_h[hidx]  = make_uint2(*(unsigned*)&c0, *(unsigned*)&c1);
}

// ---- K3: main per-entry pass, PAIR layout (2 lanes/entry, 8 outputs each) ----
__global__ void __launch_bounds__(256) k_main(
    const float* __restrict__ vals, const int* __restrict__ row,
    const int* __restrict__ col, const float* __restrict__ W,
    float* __restrict__ Y, int nnz)
{
    __shared__ float sW0[DF * DF];
    __shared__ float scall[DF], scdiag[DF];
    sW0[threadIdx.x] = W[threadIdx.x];  // blockDim == 256
    if (threadIdx.x < DF) {
        scall[threadIdx.x]  = g_call[threadIdx.x];
        scdiag[threadIdx.x] = g_cdiag[threadIdx.x];
    }
    __syncthreads();

    int gid = blockIdx.x * blockDim.x + threadIdx.x;
    int e = gid >> 1;
    if (e >= nnz) return;
    int h = gid & 1;          // half index
    int hb = h * 8;           // output base
    unsigned mask = __activemask();  // xor-1 partner always co-active

    int r = row[e], c = col[e];

    // own half of vals: 32B (2x LDG.128), coalesced across warp
    float vo[8];
    {
        const float4* vp = (const float4*)(vals + (size_t)e * DF + hb);
        *(float4*)&vo[0] = vp[0]; *(float4*)&vo[4] = vp[1];
    }
    // gathers: ONE LDG.128 per table per lane (pair's halves share a line)
    uint4 rbu = ((const uint4*)(g_rowb_h + (size_t)r * 8))[h];
    uint4 cbu = ((const uint4*)(g_colb_h + (size_t)c * 8))[h];

    float y[8], tmp[8];
#pragma unroll
    for (int k = 0; k < 8; k++) y[k] = scall[hb + k];
    h8_to_f(rbu, tmp);
#pragma unroll
    for (int k = 0; k < 8; k++) y[k] += tmp[k];
    h8_to_f(cbu, tmp);
#pragma unroll
    for (int k = 0; k < 8; k++) y[k] += tmp[k];

    if (r == c) {
        uint4 dbu = ((const uint4*)(g_diagb_h + (size_t)r * 8))[h];
        h8_to_f(dbu, tmp);
#pragma unroll
        for (int k = 0; k < 8; k++) y[k] += tmp[k] + scdiag[hb + k];
    }

    // all-gather v[16]: partner's 8 via shfl_xor(1)
    float vx[8];
#pragma unroll
    for (int k = 0; k < 8; k++) vx[k] = __shfl_xor_sync(mask, vo[k], 1);
    float vf[DF];
#pragma unroll
    for (int k = 0; k < 8; k++) {
        vf[k]     = h ? vx[k] : vo[k];
        vf[8 + k] = h ? vo[k] : vx[k];
    }

#pragma unroll
    for (int j = 0; j < DF; j++) {
        float vj = vf[j];
        float4 wA = *(const float4*)&sW0[j * DF + hb];
        float4 wB = *(const float4*)&sW0[j * DF + hb + 4];
        y[0] += vj * wA.x; y[1] += vj * wA.y; y[2] += vj * wA.z; y[3] += vj * wA.w;
        y[4] += vj * wB.x; y[5] += vj * wB.y; y[6] += vj * wB.z; y[7] += vj * wB.w;
    }

    float4* yo = (float4*)(Y + (size_t)e * DF + hb);
    yo[0] = *(float4*)&y[0]; yo[1] = *(float4*)&y[4];
}

// ---- K4: transpose scatter-add (entry per thread) ----
__global__ void __launch_bounds__(256) k_trans(
    const float* __restrict__ vals, const int* __restrict__ tin,
    const int* __restrict__ tout, const float* __restrict__ W,
    float* __restrict__ Y, int nnzt)
{
    __shared__ float sW1[DF * DF];
    sW1[threadIdx.x] = W[DF * DF + threadIdx.x];  // W[1], blockDim == 256
    __syncthreads();

    int t = blockIdx.x * blockDim.x + threadIdx.x;
    if (t >= nnzt) return;

    int ii = tin[t], io = tout[t];

    float v[DF];
    {
        const float4* vp = (const float4*)(vals + (size_t)ii * DF);
        *(float4*)&v[0] = vp[0]; *(float4*)&v[4]  = vp[1];
        *(float4*)&v[8] = vp[2]; *(float4*)&v[12] = vp[3];
    }

    float g[DF];
#pragma unroll
    for (int k = 0; k < DF; k++) g[k] = 0.f;
#pragma unroll
    for (int j = 0; j < DF; j++) {
        float vj = v[j];
#pragma unroll
        for (int k = 0; k < DF; k++) g[k] += vj * sW1[j * DF + k];
    }

    float* yp = Y + (size_t)io * DF;
    red4(yp + 0,  make_float4(g[0],  g[1],  g[2],  g[3]));
    red4(yp + 4,  make_float4(g[4],  g[5],  g[6],  g[7]));
    red4(yp + 8,  make_float4(g[8],  g[9],  g[10], g[11]));
    red4(yp + 12, make_float4(g[12], g[13], g[14], g[15]));
}

extern "C" void kernel_launch(void* const* d_in, const int* in_sizes, int n_in,
                              void* d_out, int out_size) {
    const float* vals = (const float*)d_in[0];
    const float* W    = (const float*)d_in[1];
    const float* bias = (const float*)d_in[2];
    const int* row    = (const int*)d_in[3];
    const int* col    = (const int*)d_in[4];
    const int* tin    = (const int*)d_in[5];
    const int* tout   = (const int*)d_in[6];
    float* Y = (float*)d_out;

    int nnz  = in_sizes[0] / DF;
    int nnzt = in_sizes[5];

    k_zero<<<1024, 256>>>();
    k_pool<<<2368, 256>>>(vals, row, col, nnz);
    k_node<<<(NN * 4 + 255) / 256, 256>>>(W, bias, nnz);
    k_main<<<(nnz * 2 + 255) / 256, 256>>>(vals, row, col, W, Y, nnz);
    k_trans<<<(nnzt + 255) / 256, 256>>>(vals, tin, tout, W, Y, nnzt);
}

// round 8
// speedup vs baseline: 1.5751x; 1.0454x over previous
#include <cuda_runtime.h>
#include <cuda_fp16.h>

#define NN 100000
#define DF 16

// ---- device scratch (no allocations allowed) ----
__device__ float g_D[NN * DF];                      // diag sums, fp32 (rarely hit)
__device__ __align__(16) __half2 g_PrS_h[NN * 8];   // row sums, fp16 (32B/node)
__device__ __align__(16) __half2 g_PcS_h[NN * 8];   // col sums, fp16
__device__ int   g_rcnt[NN];
__device__ int   g_ccnt[NN];
// fp16 broadcast tables: 16 halves (32B) per node
__device__ __align__(16) __half2 g_rowb_h[NN * 8];
__device__ __align__(16) __half2 g_colb_h[NN * 8];
__device__ __align__(16) __half2 g_diagb_h[NN * 8];
__device__ float g_pdsum[DF];
__device__ float g_pasum[DF];
__device__ float g_call[DF];   // all_scalar + bias[0]
__device__ float g_cdiag[DF];  // diag_scalar + bias[1]

__device__ __forceinline__ void red4(float* p, float4 v) {
    asm volatile("red.global.add.v4.f32 [%0], {%1,%2,%3,%4};"
                 :: "l"(p), "f"(v.x), "f"(v.y), "f"(v.z), "f"(v.w) : "memory");
}
__device__ __forceinline__ void red4h(__half2* p, unsigned a, unsigned b,
                                      unsigned c, unsigned d) {
    asm volatile("red.global.add.noftz.v4.f16x2 [%0], {%1,%2,%3,%4};"
                 :: "l"(p), "r"(a), "r"(b), "r"(c), "r"(d) : "memory");
}

// ---- K0: zero scratch ----
__global__ void k_zero() {
    int tid = blockIdx.x * blockDim.x + threadIdx.x;
    int stride = gridDim.x * blockDim.x;
    float4 z = make_float4(0.f, 0.f, 0.f, 0.f);
    uint4 zu = make_uint4(0, 0, 0, 0);
    for (int t = tid; t < NN * 4; t += stride) ((float4*)g_D)[t] = z;
    for (int t = tid; t < NN * 2; t += stride) {
        ((uint4*)g_PrS_h)[t] = zu;
        ((uint4*)g_PcS_h)[t] = zu;
    }
    for (int t = tid; t < NN; t += stride) { g_rcnt[t] = 0; g_ccnt[t] = 0; }
    if (blockIdx.x == 0 && threadIdx.x < DF) {
        g_pdsum[threadIdx.x] = 0.f; g_pasum[threadIdx.x] = 0.f;
    }
}

// ---- K1: pooling pass (fp16 vector REDs for Pr/Pc) ----
__global__ void __launch_bounds__(256) k_pool(
    const float* __restrict__ vals, const int* __restrict__ row,
    const int* __restrict__ col, int nnz)
{
    __shared__ float s_pa[DF], s_pd[DF];
    if (threadIdx.x < DF) { s_pa[threadIdx.x] = 0.f; s_pd[threadIdx.x] = 0.f; }
    __syncthreads();

    float pa[DF], pd[DF];
#pragma unroll
    for (int k = 0; k < DF; k++) { pa[k] = 0.f; pd[k] = 0.f; }

    int tid = blockIdx.x * blockDim.x + threadIdx.x;
    int stride = gridDim.x * blockDim.x;
    for (int i = tid; i < nnz; i += stride) {
        int r = row[i], c = col[i];
        const float4* vp = (const float4*)(vals + (size_t)i * DF);
        float4 v0 = vp[0], v1 = vp[1], v2 = vp[2], v3 = vp[3];

        __half2 hv[8];
        hv[0] = __floats2half2_rn(v0.x, v0.y); hv[1] = __floats2half2_rn(v0.z, v0.w);
        hv[2] = __floats2half2_rn(v1.x, v1.y); hv[3] = __floats2half2_rn(v1.z, v1.w);
        hv[4] = __floats2half2_rn(v2.x, v2.y); hv[5] = __floats2half2_rn(v2.z, v2.w);
        hv[6] = __floats2half2_rn(v3.x, v3.y); hv[7] = __floats2half2_rn(v3.z, v3.w);
        const unsigned* hu = (const unsigned*)hv;

        __half2* pr = g_PrS_h + (size_t)r * 8;
        red4h(pr + 0, hu[0], hu[1], hu[2], hu[3]);
        red4h(pr + 4, hu[4], hu[5], hu[6], hu[7]);
        __half2* pc = g_PcS_h + (size_t)c * 8;
        red4h(pc + 0, hu[0], hu[1], hu[2], hu[3]);
        red4h(pc + 4, hu[4], hu[5], hu[6], hu[7]);
        atomicAdd(&g_rcnt[r], 1);
        atomicAdd(&g_ccnt[c], 1);

        pa[0]  += v0.x; pa[1]  += v0.y; pa[2]  += v0.z; pa[3]  += v0.w;
        pa[4]  += v1.x; pa[5]  += v1.y; pa[6]  += v1.z; pa[7]  += v1.w;
        pa[8]  += v2.x; pa[9]  += v2.y; pa[10] += v2.z; pa[11] += v2.w;
        pa[12] += v3.x; pa[13] += v3.y; pa[14] += v3.z; pa[15] += v3.w;

        if (r == c) {
            float* dd = &g_D[(size_t)r * DF];
            red4(dd + 0, v0); red4(dd + 4, v1); red4(dd + 8, v2); red4(dd + 12, v3);
            pd[0]  += v0.x; pd[1]  += v0.y; pd[2]  += v0.z; pd[3]  += v0.w;
            pd[4]  += v1.x; pd[5]  += v1.y; pd[6]  += v1.z; pd[7]  += v1.w;
            pd[8]  += v2.x; pd[9]  += v2.y; pd[10] += v2.z; pd[11] += v2.w;
            pd[12] += v3.x; pd[13] += v3.y; pd[14] += v3.z; pd[15] += v3.w;
        }
    }

#pragma unroll
    for (int k = 0; k < DF; k++) {
#pragma unroll
        for (int o = 16; o > 0; o >>= 1) {
            pa[k] += __shfl_down_sync(0xffffffffu, pa[k], o);
            pd[k] += __shfl_down_sync(0xffffffffu, pd[k], o);
        }
    }
    if ((threadIdx.x & 31) == 0) {
#pragma unroll
        for (int k = 0; k < DF; k++) {
            atomicAdd(&s_pa[k], pa[k]);
            atomicAdd(&s_pd[k], pd[k]);
        }
    }
    __syncthreads();
    if (threadIdx.x < DF) {
        atomicAdd(&g_pasum[threadIdx.x], s_pa[threadIdx.x]);
        atomicAdd(&g_pdsum[threadIdx.x], s_pd[threadIdx.x]);
    }
}

// unpack a uint4 (8 halves) into f[8]
__device__ __forceinline__ void h8_to_f(const uint4& u, float* f) {
    const unsigned* p = &u.x;
#pragma unroll
    for (int i = 0; i < 4; i++) {
        float2 t = __half22float2(*(const __half2*)&p[i]);
        f[i * 2 + 0] = t.x; f[i * 2 + 1] = t.y;
    }
}

// ---- K2: per-node broadcast vectors (fp16 in/out) + (block 0) scalars ----
__global__ void __launch_bounds__(256) k_node(const float* __restrict__ W,
                                              const float* __restrict__ bias,
                                              int nnz) {
    if (blockIdx.x == 0 && threadIdx.x < DF) {
        int k = threadIdx.x;
        float inv_n = 1.f / (float)NN;
        float inv_e = 1.f / (float)nnz;
        float ds = 0.f, as = 0.f;
#pragma unroll
        for (int j = 0; j < DF; j++) {
            float pdj = g_pdsum[j] * inv_n;
            float paj = g_pasum[j] * inv_e;
            ds += pdj * W[11 * 256 + j * DF + k] + paj * W[13 * 256 + j * DF + k];
            as += pdj * W[12 * 256 + j * DF + k] + paj * W[14 * 256 + j * DF + k];
        }
        g_call[k]  = as + bias[k];
        g_cdiag[k] = ds + bias[DF + k];
    }

    __shared__ float sW[9 * DF * DF];  // W2..W10
    for (int t = threadIdx.x; t < 9 * DF * DF; t += blockDim.x)
        sW[t] = W[2 * DF * DF + t];
    __syncthreads();

    int gid = blockIdx.x * blockDim.x + threadIdx.x;
    int n = gid >> 2;
    int q = (gid & 3) * 4;
    if (n >= NN) return;

    float rinv = 1.f / (float)max(g_rcnt[n], 1);
    float cinv = 1.f / (float)max(g_ccnt[n], 1);

    float dv[DF], prv[DF], pcv[DF];
    {
        const float4* dp  = (const float4*)&g_D[(size_t)n * DF];
        *(float4*)&dv[0]  = dp[0];  *(float4*)&dv[4]  = dp[1];
        *(float4*)&dv[8]  = dp[2];  *(float4*)&dv[12] = dp[3];
        const uint4* prp = (const uint4*)(g_PrS_h + (size_t)n * 8);
        const uint4* pcp = (const uint4*)(g_PcS_h + (size_t)n * 8);
        uint4 a = prp[0], b = prp[1], cgl = pcp[0], d = pcp[1];
        h8_to_f(a, &prv[0]); h8_to_f(b, &prv[8]);
        h8_to_f(cgl, &pcv[0]); h8_to_f(d, &pcv[8]);
    }
#pragma unroll
    for (int k = 0; k < DF; k++) { prv[k] *= rinv; pcv[k] *= cinv; }

    float db[4], rb[4], cb[4];
#pragma unroll
    for (int t = 0; t < 4; t++) { db[t] = 0.f; rb[t] = 0.f; cb[t] = 0.f; }

#pragma unroll
    for (int j = 0; j < DF; j++) {
        float d = dv[j], pr = prv[j], pc = pcv[j];
        float4 w2 = *(const float4*)&sW[(0 * DF + j) * DF + q];
        float4 w3 = *(const float4*)&sW[(1 * DF + j) * DF + q];
        float4 w4 = *(const float4*)&sW[(2 * DF + j) * DF + q];
        float4 w5 = *(const float4*)&sW[(3 * DF + j) * DF + q];
        float4 w6 = *(const float4*)&sW[(4 * DF + j) * DF + q];
        float4 w7 = *(const float4*)&sW[(5 * DF + j) * DF + q];
        float4 w8 = *(const float4*)&sW[(6 * DF + j) * DF + q];
        float4 w9 = *(const float4*)&sW[(7 * DF + j) * DF + q];
        float4 wa = *(const float4*)&sW[(8 * DF + j) * DF + q];
        db[0] += d * w2.x + pr * w5.x + pc * w8.x;
        db[1] += d * w2.y + pr * w5.y + pc * w8.y;
        db[2] += d * w2.z + pr * w5.z + pc * w8.z;
        db[3] += d * w2.w + pr * w5.w + pc * w8.w;
        rb[0] += d * w3.x + pr * w6.x + pc * w9.x;
        rb[1] += d * w3.y + pr * w6.y + pc * w9.y;
        rb[2] += d * w3.z + pr * w6.z + pc * w9.z;
        rb[3] += d * w3.w + pr * w6.w + pc * w9.w;
        cb[0] += d * w4.x + pr * w7.x + pc * wa.x;
        cb[1] += d * w4.y + pr * w7.y + pc * wa.y;
        cb[2] += d * w4.z + pr * w7.z + pc * wa.z;
        cb[3] += d * w4.w + pr * w7.w + pc * wa.w;
    }

    int hidx = n * 8 + (q >> 1);
    __half2 d0 = __floats2half2_rn(db[0], db[1]);
    __half2 d1 = __floats2half2_rn(db[2], db[3]);
    __half2 r0 = __floats2half2_rn(rb[0], rb[1]);
    __half2 r1 = __floats2half2_rn(rb[2], rb[3]);
    __half2 c0 = __floats2half2_rn(cb[0], cb[1]);
    __half2 c1 = __floats2half2_rn(cb[2], cb[3]);
    *(uint2*)&g_diagb_h[hidx] = make_uint2(*(unsigned*)&d0, *(unsigned*)&d1);
    *(uint2*)&g_rowb_h[hidx]  = make_uint2(*(unsigned*)&r0, *(unsigned*)&r1);
    *(uint2*)&g_colb_h[hidx]  = make_uint2(*(unsigned*)&c0, *(unsigned*)&c1);
}

// ---- K3: main per-entry pass, PAIR layout, occupancy-forced ----
__global__ void __launch_bounds__(256, 6) k_main(
    const float* __restrict__ vals, const int* __restrict__ row,
    const int* __restrict__ col, const float* __restrict__ W,
    float* __restrict__ Y, int nnz)
{
    __shared__ float sW0[DF * DF];
    __shared__ float scall[DF], scdiag[DF];
    sW0[threadIdx.x] = W[threadIdx.x];  // blockDim == 256
    if (threadIdx.x < DF) {
        scall[threadIdx.x]  = g_call[threadIdx.x];
        scdiag[threadIdx.x] = g_cdiag[threadIdx.x];
    }
    __syncthreads();

    int gid = blockIdx.x * blockDim.x + threadIdx.x;
    int e = gid >> 1;
    if (e >= nnz) return;
    int h = gid & 1;
    int hb = h * 8;
    unsigned mask = __activemask();

    int r = row[e], c = col[e];

    float vo[8];
    {
        const float4* vp = (const float4*)(vals + (size_t)e * DF + hb);
        *(float4*)&vo[0] = vp[0]; *(float4*)&vo[4] = vp[1];
    }
    uint4 rbu = ((const uint4*)(g_rowb_h + (size_t)r * 8))[h];
    uint4 cbu = ((const uint4*)(g_colb_h + (size_t)c * 8))[h];

    float y[8], tmp[8];
#pragma unroll
    for (int k = 0; k < 8; k++) y[k] = scall[hb + k];
    h8_to_f(rbu, tmp);
#pragma unroll
    for (int k = 0; k < 8; k++) y[k] += tmp[k];
    h8_to_f(cbu, tmp);
#pragma unroll
    for (int k = 0; k < 8; k++) y[k] += tmp[k];

    if (r == c) {
        uint4 dbu = ((const uint4*)(g_diagb_h + (size_t)r * 8))[h];
        h8_to_f(dbu, tmp);
#pragma unroll
        for (int k = 0; k < 8; k++) y[k] += tmp[k] + scdiag[hb + k];
    }

    float vx[8];
#pragma unroll
    for (int k = 0; k < 8; k++) vx[k] = __shfl_xor_sync(mask, vo[k], 1);
    float vf[DF];
#pragma unroll
    for (int k = 0; k < 8; k++) {
        vf[k]     = h ? vx[k] : vo[k];
        vf[8 + k] = h ? vo[k] : vx[k];
    }

#pragma unroll
    for (int j = 0; j < DF; j++) {
        float vj = vf[j];
        float4 wA = *(const float4*)&sW0[j * DF + hb];
        float4 wB = *(const float4*)&sW0[j * DF + hb + 4];
        y[0] += vj * wA.x; y[1] += vj * wA.y; y[2] += vj * wA.z; y[3] += vj * wA.w;
        y[4] += vj * wB.x; y[5] += vj * wB.y; y[6] += vj * wB.z; y[7] += vj * wB.w;
    }

    float4* yo = (float4*)(Y + (size_t)e * DF + hb);
    yo[0] = *(float4*)&y[0]; yo[1] = *(float4*)&y[4];
}

// ---- K4: transpose scatter-add, PAIR layout ----
__global__ void __launch_bounds__(256, 6) k_trans(
    const float* __restrict__ vals, const int* __restrict__ tin,
    const int* __restrict__ tout, const float* __restrict__ W,
    float* __restrict__ Y, int nnzt)
{
    __shared__ float sW1[DF * DF];
    sW1[threadIdx.x] = W[DF * DF + threadIdx.x];  // W[1], blockDim == 256
    __syncthreads();

    int gid = blockIdx.x * blockDim.x + threadIdx.x;
    int t = gid >> 1;
    if (t >= nnzt) return;
    int h = gid & 1;
    int hb = h * 8;
    unsigned mask = __activemask();

    int ii = tin[t], io = tout[t];

    // own half of the gathered vals row: 32B (2x LDG.128); pair shares the line
    float vo[8];
    {
        const float4* vp = (const float4*)(vals + (size_t)ii * DF + hb);
        *(float4*)&vo[0] = vp[0]; *(float4*)&vo[4] = vp[1];
    }
    float vx[8];
#pragma unroll
    for (int k = 0; k < 8; k++) vx[k] = __shfl_xor_sync(mask, vo[k], 1);
    float vf[DF];
#pragma unroll
    for (int k = 0; k < 8; k++) {
        vf[k]     = h ? vx[k] : vo[k];
        vf[8 + k] = h ? vo[k] : vx[k];
    }

    float g[8];
#pragma unroll
    for (int k = 0; k < 8; k++) g[k] = 0.f;
#pragma unroll
    for (int j = 0; j < DF; j++) {
        float vj = vf[j];
        float4 wA = *(const float4*)&sW1[j * DF + hb];
        float4 wB = *(const float4*)&sW1[j * DF + hb + 4];
        g[0] += vj * wA.x; g[1] += vj * wA.y; g[2] += vj * wA.z; g[3] += vj * wA.w;
        g[4] += vj * wB.x; g[5] += vj * wB.y; g[6] += vj * wB.z; g[7] += vj * wB.w;
    }

    float* yp = Y + (size_t)io * DF + hb;
    red4(yp + 0, make_float4(g[0], g[1], g[2], g[3]));
    red4(yp + 4, make_float4(g[4], g[5], g[6], g[7]));
}

extern "C" void kernel_launch(void* const* d_in, const int* in_sizes, int n_in,
                              void* d_out, int out_size) {
    const float* vals = (const float*)d_in[0];
    const float* W    = (const float*)d_in[1];
    const float* bias = (const float*)d_in[2];
    const int* row    = (const int*)d_in[3];
    const int* col    = (const int*)d_in[4];
    const int* tin    = (const int*)d_in[5];
    const int* tout   = (const int*)d_in[6];
    float* Y = (float*)d_out;

    int nnz  = in_sizes[0] / DF;
    int nnzt = in_sizes[5];

    k_zero<<<1024, 256>>>();
    k_pool<<<2368, 256>>>(vals, row, col, nnz);
    k_node<<<(NN * 4 + 255) / 256, 256>>>(W, bias, nnz);
    k_main<<<(nnz * 2 + 255) / 256, 256>>>(vals, row, col, W, Y, nnz);
    k_trans<<<(nnzt * 2 + 255) / 256, 256>>>(vals, tin, tout, W, Y, nnzt);
}